// round 8
// baseline (speedup 1.0000x reference)
#include <cuda_runtime.h>
#include <cuda_bf16.h>
#include <cstdint>

#define N_ROWS 32768
#define K_EMB  8192
#define D_DIM  512
#define BM 128
#define BN 128
#define BK 64                    // bf16 elems per chunk (128B rows)
#define NKC (D_DIM / BK)         // 8 k-chunks
#define NTILES (K_EMB / BN)      // 64 n-tiles
#define TILE_B 16384             // 128 rows * 128B
#define STAGE_B (2 * TILE_B)     // A + B
#define NSTAGE 3
#define GRID_P 296               // 2 CTAs x 148 SMs, all resident
#define NT_U 8                   // n-tiles per work unit
#define NUNITS (256 * 8)         // (m-tile, n-eighth) units = 2048
#define SMEM_HDR 1024            // barriers
#define SMEM_MRG 4096            // 128 rows x 4 (d,i) pairs
#define SMEM_STAGES (SMEM_HDR + SMEM_MRG)
#define SMEM_TOTAL (SMEM_STAGES + NSTAGE * STAGE_B)   // 103424 -> 2 CTA/SM

__device__ __align__(1024) __nv_bfloat16 g_A[(size_t)N_ROWS * D_DIM]; // tiled/swizzled
__device__ __align__(1024) __nv_bfloat16 g_B[(size_t)K_EMB * D_DIM];  // tiled/swizzled
__device__ float g_enorm[K_EMB];
__device__ float g_pd[(size_t)N_ROWS * 16];
__device__ int   g_pi[(size_t)N_ROWS * 16];
__device__ int   g_bestIdx[N_ROWS];

// ---------------------------------------------------------------------------
// PTX helpers (baseline features only — ptxas rejects tcgen05 on compute_103)
// ---------------------------------------------------------------------------
__device__ __forceinline__ uint32_t smem_u32(const void* p) {
    uint32_t a;
    asm("{ .reg .u64 t; cvta.to.shared.u64 t, %1; cvt.u32.u64 %0, t; }" : "=r"(a) : "l"(p));
    return a;
}
__device__ __forceinline__ void mbar_init(uint32_t m, uint32_t cnt) {
    asm volatile("mbarrier.init.shared.b64 [%0], %1;" :: "r"(m), "r"(cnt) : "memory");
}
__device__ __forceinline__ void mbar_arrive(uint32_t m) {
    asm volatile("mbarrier.arrive.shared.b64 _, [%0];" :: "r"(m) : "memory");
}
__device__ __forceinline__ void mbar_expect_tx(uint32_t m, uint32_t bytes) {
    asm volatile("mbarrier.arrive.expect_tx.shared.b64 _, [%0], %1;" :: "r"(m), "r"(bytes) : "memory");
}
__device__ __forceinline__ void mbar_wait(uint32_t m, uint32_t parity) {
    asm volatile(
        "{\n\t.reg .pred P;\n"
        "W_%=:\n\t"
        "mbarrier.try_wait.parity.acquire.cta.shared::cta.b64 P, [%0], %1, 0x989680;\n\t"
        "@P bra D_%=;\n\t"
        "bra W_%=;\n"
        "D_%=:\n\t}"
        :: "r"(m), "r"(parity) : "memory");
}
__device__ __forceinline__ void bulk_g2s(uint32_t dst, const void* src, uint32_t bytes, uint32_t mbar) {
    asm volatile(
        "cp.async.bulk.shared::cluster.global.mbarrier::complete_tx::bytes [%0], [%1], %2, [%3];"
        :: "r"(dst), "l"(src), "r"(bytes), "r"(mbar) : "memory");
}
__device__ __forceinline__ void ldsm4(uint32_t* r, uint32_t addr) {
    asm volatile("ldmatrix.sync.aligned.m8n8.x4.shared.b16 {%0,%1,%2,%3}, [%4];"
                 : "=r"(r[0]), "=r"(r[1]), "=r"(r[2]), "=r"(r[3]) : "r"(addr));
}
__device__ __forceinline__ void mma16816(float* c, const uint32_t* a, uint32_t b0, uint32_t b1) {
    asm volatile(
        "mma.sync.aligned.m16n8k16.row.col.f32.bf16.bf16.f32 "
        "{%0,%1,%2,%3}, {%4,%5,%6,%7}, {%8,%9}, {%0,%1,%2,%3};"
        : "+f"(c[0]), "+f"(c[1]), "+f"(c[2]), "+f"(c[3])
        : "r"(a[0]), "r"(a[1]), "r"(a[2]), "r"(a[3]), "r"(b0), "r"(b1));
}

// ---------------------------------------------------------------------------
// ||e_k||^2 — warp per row, float4
// ---------------------------------------------------------------------------
__global__ void enorm_kernel(const float* __restrict__ e) {
    const int row = blockIdx.x * 8 + (threadIdx.x >> 5);
    const int lane = threadIdx.x & 31;
    const float4* r4 = (const float4*)(e + (size_t)row * D_DIM);
    float s = 0.f;
#pragma unroll
    for (int d4 = lane; d4 < 128; d4 += 32) {
        float4 v = r4[d4];
        s += v.x * v.x + v.y * v.y + v.z * v.z + v.w * v.w;
    }
#pragma unroll
    for (int o = 16; o; o >>= 1) s += __shfl_down_sync(0xffffffffu, s, o);
    if (lane == 0) g_enorm[row] = s;
}

// ---------------------------------------------------------------------------
// fp32 -> bf16, pre-swizzled tile layout: tile = 128 rows x 64 cols (128B/row),
// SW128 XOR swizzle.
// ---------------------------------------------------------------------------
__device__ __forceinline__ uint4 pack8h(const float* v) {
    unsigned short hh[8];
#pragma unroll
    for (int i = 0; i < 8; i++) hh[i] = __bfloat16_as_ushort(__float2bfloat16(v[i]));
    uint4 H;
    H.x = hh[0] | ((uint32_t)hh[1] << 16); H.y = hh[2] | ((uint32_t)hh[3] << 16);
    H.z = hh[4] | ((uint32_t)hh[5] << 16); H.w = hh[6] | ((uint32_t)hh[7] << 16);
    return H;
}

__global__ void split_x_kernel(const float* __restrict__ x) {
    int gid = blockIdx.x * 256 + threadIdx.x;   // N_ROWS*64 threads
    int n = gid >> 6, d8 = gid & 63;
    const float4* xp = (const float4*)(x + (size_t)n * D_DIM + d8 * 8);
    float4 a = xp[0], b = xp[1];
    float v[8] = {a.x, a.y, a.z, a.w, b.x, b.y, b.z, b.w};
    uint4 H = pack8h(v);
    int tile = (n >> 7) * NKC + (d8 >> 3);
    int boff = (n & 127) * 128 + (d8 & 7) * 16;
    boff ^= (boff >> 3) & 0x70;
    *(uint4*)((char*)g_A + (size_t)tile * TILE_B + boff) = H;
}

__global__ void split_e_kernel(const float* __restrict__ e) {
    int gid = blockIdx.x * 256 + threadIdx.x;   // K_EMB*64 threads
    int k = gid >> 6, d8 = gid & 63;
    const float4* ep = (const float4*)(e + (size_t)k * D_DIM + d8 * 8);
    float4 a = ep[0], b = ep[1];
    float v[8] = {a.x, a.y, a.z, a.w, b.x, b.y, b.z, b.w};
    uint4 H = pack8h(v);
    int tile = (k >> 7) * NKC + (d8 >> 3);
    int boff = (k & 127) * 128 + (d8 & 7) * 16;
    boff ^= (boff >> 3) & 0x70;
    *(uint4*)((char*)g_B + (size_t)tile * TILE_B + boff) = H;
}

// ---------------------------------------------------------------------------
// Persistent HMMA GEMM + per-unit top-2 per row.
// 296 CTAs (2/SM, all resident). Units = (m-tile, n-eighth), static stride-296.
// Per-warp mbarrier pipeline with EARLY stage release: each warp arrives on
// empty[s] right after its last ldmatrix from stage s (release-ordered), before
// its tensor-pipe-backpressured MMA issues; producer wait+issue also hoisted
// before the last 16 MMAs. Warp grid 4(m) x 2(n); warp tile 32m x 64n.
// ---------------------------------------------------------------------------
__global__ __launch_bounds__(256, 2) void gemm_argmin_kernel() {
    extern __shared__ __align__(1024) char smem[];
    const uint32_t sb = smem_u32(smem);
    const int tid = threadIdx.x, l = tid & 31, w = tid >> 5;
    const int wm = w & 3, wn = w >> 2;
    const int b = blockIdx.x;
    const int cnt = (b < (NUNITS % GRID_P)) ? (NUNITS / GRID_P + 1) : (NUNITS / GRID_P);
    const int END = cnt * (NT_U * NKC);            // chunks in this CTA's stream

    // full[s] @ sb + s*8 ; empty[s] @ sb + 64 + s*8
    if (tid == 0) {
#pragma unroll
        for (int s = 0; s < NSTAGE; s++) { mbar_init(sb + s * 8, 1); mbar_init(sb + 64 + s * 8, 8); }
    }
    __syncthreads();

    const char* Ab = (const char*)g_A;
    const char* Bb = (const char*)g_B;
    auto issue = [&](int g) {
        int j = g >> 6, r = g & 63;
        int u = b + j * GRID_P;
        int m = u >> 3, ne = u & 7;
        int nt = ne * NT_U + (r >> 3), kc = r & 7;
        int s = g % NSTAGE;
        uint32_t st = sb + SMEM_STAGES + s * STAGE_B;
        mbar_expect_tx(sb + s * 8, STAGE_B);
        bulk_g2s(st,          Ab + ((size_t)m * NKC + kc) * TILE_B, TILE_B, sb + s * 8);
        bulk_g2s(st + TILE_B, Bb + ((size_t)nt * NKC + kc) * TILE_B, TILE_B, sb + s * 8);
    };
    if (tid == 0) { issue(0); issue(1); issue(2); }   // END >= 384 always

    // per-thread addressing constants
    const int lrA = (l & 7) + ((l >> 3) & 1) * 8;            // A row-in-16
    const int lrB = (l & 7) + ((l >> 4) & 1) * 8;            // B row-in-16
    const int cA  = (l >> 4);                                 // A col16 offset
    const int cB  = ((l >> 3) & 1);                           // B col16 offset
    const int swz = (l & 7);
    const uint32_t rA0 = (uint32_t)(wm * 32 + lrA) * 128;
    const uint32_t rA1 = rA0 + 16 * 128;
    uint32_t rB[4];
#pragma unroll
    for (int nb = 0; nb < 4; nb++) rB[nb] = (uint32_t)(wn * 64 + nb * 16 + lrB) * 128;

    float* sMD = (float*)(smem + SMEM_HDR);                   // [128][4]
    int*   sMI = (int*)(smem + SMEM_HDR + 128 * 4 * 4);       // [128][4]

    int g = 0;
    for (int j = 0; j < cnt; ++j) {
        const int u = b + j * GRID_P;
        const int m = u >> 3, ne = u & 7;

        float td[4][2]; int ti[4][2];
#pragma unroll
        for (int i = 0; i < 4; i++) { td[i][0] = td[i][1] = 3.4e38f; ti[i][0] = ti[i][1] = 0; }

        for (int ntl = 0; ntl < NT_U; ++ntl) {
            float acc[2][8][4];
#pragma unroll
            for (int mi = 0; mi < 2; mi++)
#pragma unroll
                for (int nf = 0; nf < 8; nf++)
#pragma unroll
                    for (int q = 0; q < 4; q++) acc[mi][nf][q] = 0.f;

            uint32_t fa[2][2][4];     // [buf][mi][frag]
            uint32_t fb[2][4][4];     // [buf][nb][frag]

            for (int kc = 0; kc < NKC; ++kc, ++g) {
                const int s = g % NSTAGE;
                const uint32_t phase = (uint32_t)((g / NSTAGE) & 1);
                mbar_wait(sb + s * 8, phase);
                const uint32_t aB = sb + SMEM_STAGES + s * STAGE_B;
                const uint32_t bB = aB + TILE_B;

                auto LD = [&](int buf, int ks) {
                    uint32_t ca = ((uint32_t)((ks * 2 + cA) ^ swz)) << 4;
                    uint32_t cb = ((uint32_t)((ks * 2 + cB) ^ swz)) << 4;
                    ldsm4(fa[buf][0], aB + rA0 + ca);
                    ldsm4(fa[buf][1], aB + rA1 + ca);
#pragma unroll
                    for (int nb = 0; nb < 4; nb++) ldsm4(fb[buf][nb], bB + rB[nb] + cb);
                };
                auto MM = [&](int buf) {
#pragma unroll
                    for (int nb = 0; nb < 4; nb++)
#pragma unroll
                        for (int mi = 0; mi < 2; mi++) {
                            mma16816(acc[mi][nb * 2 + 0], fa[buf][mi], fb[buf][nb][0], fb[buf][nb][1]);
                            mma16816(acc[mi][nb * 2 + 1], fa[buf][mi], fb[buf][nb][2], fb[buf][nb][3]);
                        }
                };

                LD(0, 0);
                LD(1, 1);
                MM(0);                       // ks=0
                LD(0, 2);
                MM(1);                       // ks=1
                LD(1, 3);
                // all smem reads for this stage are issued — release stage early
                if (l == 0) mbar_arrive(sb + 64 + s * 8);
                if (tid == 0 && g + 3 < END) {
                    mbar_wait(sb + 64 + s * 8, phase);   // other warps' post-ldsm arrivals
                    issue(g + 3);
                }
                MM(0);                       // ks=2
                MM(1);                       // ks=3
            }

            // epilogue: dist = ||e||^2 - 2*dot ; per-thread top-2 per row
            const int colb = (ne * NT_U + ntl) * BN + wn * 64 + (l & 3) * 2;
#pragma unroll
            for (int mi = 0; mi < 2; mi++)
#pragma unroll
                for (int r2 = 0; r2 < 2; r2++) {
                    const int ri = mi * 2 + r2;
#pragma unroll
                    for (int nf = 0; nf < 8; nf++)
#pragma unroll
                        for (int d = 0; d < 2; d++) {
                            const int col = colb + nf * 8 + d;
                            float dist = __ldg(&g_enorm[col]) - 2.f * acc[mi][nf][r2 * 2 + d];
                            if (dist < td[ri][0]) {
                                td[ri][1] = td[ri][0]; ti[ri][1] = ti[ri][0];
                                td[ri][0] = dist;      ti[ri][0] = col;
                            } else if (dist < td[ri][1]) {
                                td[ri][1] = dist; ti[ri][1] = col;
                            }
                        }
                }
        }

        // intra-warp merge: 4-lane groups (same rows, different cols) -> top-2
#pragma unroll
        for (int ri = 0; ri < 4; ++ri) {
            float d0 = td[ri][0], d1 = td[ri][1];
            int   i0 = ti[ri][0], i1 = ti[ri][1];
#pragma unroll
            for (int off = 1; off <= 2; off <<= 1) {
                float od0 = __shfl_xor_sync(0xffffffffu, d0, off);
                float od1 = __shfl_xor_sync(0xffffffffu, d1, off);
                int   oi0 = __shfl_xor_sync(0xffffffffu, i0, off);
                int   oi1 = __shfl_xor_sync(0xffffffffu, i1, off);
                if (od0 < d0 || (od0 == d0 && oi0 < i0)) {
                    float nd1; int ni1;
                    if (d0 < od1 || (d0 == od1 && i0 < oi1)) { nd1 = d0; ni1 = i0; }
                    else                                      { nd1 = od1; ni1 = oi1; }
                    d0 = od0; i0 = oi0; d1 = nd1; i1 = ni1;
                } else if (od0 < d1 || (od0 == d1 && oi0 < i1)) {
                    d1 = od0; i1 = oi0;
                }
            }
            if ((l & 3) == 0) {
                const int row = wm * 32 + (ri >> 1) * 16 + (ri & 1) * 8 + (l >> 2);
                sMD[row * 4 + wn * 2]     = d0; sMI[row * 4 + wn * 2]     = i0;
                sMD[row * 4 + wn * 2 + 1] = d1; sMI[row * 4 + wn * 2 + 1] = i1;
            }
        }
        __syncthreads();
        if (tid < BM) {
            float dv[4]; int iv[4];
#pragma unroll
            for (int t = 0; t < 4; t++) { dv[t] = sMD[tid * 4 + t]; iv[t] = sMI[tid * 4 + t]; }
            const size_t rg = (size_t)(m * BM + tid) * 16 + ne * 2;
#pragma unroll
            for (int q = 0; q < 2; q++) {
                float bd = dv[0]; int bi = iv[0], bt = 0;
#pragma unroll
                for (int t = 1; t < 4; t++)
                    if (dv[t] < bd || (dv[t] == bd && iv[t] < bi)) { bd = dv[t]; bi = iv[t]; bt = t; }
                g_pd[rg + q] = bd; g_pi[rg + q] = bi;
                dv[bt] = 3.4e38f;
            }
        }
        __syncthreads();   // protect sMD/sMI reuse by next unit
    }
}

// ---------------------------------------------------------------------------
// Fused tail: top-4 of 16 candidates -> exact fp32 rescore -> writeout.
// One warp per row.
// ---------------------------------------------------------------------------
__global__ void candwrite_kernel(const float* __restrict__ x,
                                 const float* __restrict__ e,
                                 float* __restrict__ out) {
    const int row = blockIdx.x * 8 + (threadIdx.x >> 5);
    const int lane = threadIdx.x & 31;

    int c[4];
    if (lane == 0) {
        float dv[16]; int iv[16];
#pragma unroll
        for (int t = 0; t < 16; t++) {
            dv[t] = g_pd[(size_t)row * 16 + t];
            iv[t] = g_pi[(size_t)row * 16 + t];
        }
#pragma unroll
        for (int q = 0; q < 4; q++) {
            float bd = dv[0]; int bi = iv[0], bt = 0;
#pragma unroll
            for (int t = 1; t < 16; t++)
                if (dv[t] < bd || (dv[t] == bd && iv[t] < bi)) { bd = dv[t]; bi = iv[t]; bt = t; }
            c[q] = bi;
            dv[bt] = 3.4e38f;
        }
    }
#pragma unroll
    for (int q = 0; q < 4; q++) c[q] = __shfl_sync(0xffffffffu, c[q], 0);

    const float4* x4 = (const float4*)(x + (size_t)row * D_DIM);
    float s[4] = {0.f, 0.f, 0.f, 0.f};
#pragma unroll
    for (int d4 = lane; d4 < 128; d4 += 32) {
        float4 xv = x4[d4];
#pragma unroll
        for (int q = 0; q < 4; q++) {
            float4 ev = ((const float4*)(e + (size_t)c[q] * D_DIM))[d4];
            s[q] += xv.x * ev.x + xv.y * ev.y + xv.z * ev.z + xv.w * ev.w;
        }
    }
#pragma unroll
    for (int o = 16; o; o >>= 1)
#pragma unroll
        for (int q = 0; q < 4; q++) s[q] += __shfl_down_sync(0xffffffffu, s[q], o);

    int best = 0;
    if (lane == 0) {
        float bd = 3.4e38f; int bi = 0x7fffffff;
#pragma unroll
        for (int q = 0; q < 4; q++) {
            float dq = g_enorm[c[q]] - 2.f * s[q];
            if (dq < bd || (dq == bd && c[q] < bi)) { bd = dq; bi = c[q]; }
        }
        best = bi;
        g_bestIdx[row] = bi;
    }
    best = __shfl_sync(0xffffffffu, best, 0);

    const int ND4 = N_ROWS * (D_DIM / 4);
    const float4* e4 = (const float4*)(e + (size_t)best * D_DIM);
    float4* o4 = (float4*)out;
#pragma unroll
    for (int d4 = lane; d4 < 128; d4 += 32) {
        float4 xv = x4[d4];
        float4 ev = e4[d4];
        float4 xq;
        xq.x = xv.x + (ev.x - xv.x);
        xq.y = xv.y + (ev.y - xv.y);
        xq.z = xv.z + (ev.z - xv.z);
        xq.w = xv.w + (ev.w - xv.w);
        const int i = row * 128 + d4;
        o4[i] = xq;               // x_q
        o4[ND4 + i] = xv;         // z_e
        o4[2 * ND4 + i] = ev;     // z_q
    }
}

extern "C" void kernel_launch(void* const* d_in, const int* in_sizes, int n_in,
                              void* d_out, int out_size) {
    const float* x = (const float*)d_in[0];
    const float* e = (const float*)d_in[1];
    float* out = (float*)d_out;

    cudaFuncSetAttribute(gemm_argmin_kernel,
                         cudaFuncAttributeMaxDynamicSharedMemorySize, SMEM_TOTAL);

    split_x_kernel<<<N_ROWS * 64 / 256, 256>>>(x);
    split_e_kernel<<<K_EMB * 64 / 256, 256>>>(e);
    enorm_kernel<<<K_EMB / 8, 256>>>(e);
    gemm_argmin_kernel<<<GRID_P, 256, SMEM_TOTAL>>>();
    candwrite_kernel<<<N_ROWS / 8, 256>>>(x, e, out);
}

// round 9
// speedup vs baseline: 1.1095x; 1.1095x over previous
#include <cuda_runtime.h>
#include <cuda_bf16.h>
#include <cstdint>

#define N_ROWS 32768
#define K_EMB  8192
#define D_DIM  512
#define BM 256                   // x rows per CTA (two 128-row A tiles)
#define BN 128
#define BK 64                    // bf16 elems per chunk (128B rows)
#define NKC (D_DIM / BK)         // 8 k-chunks
#define TILE_B 16384             // 128 rows * 128B
#define A_STAGE_B 32768          // two A tiles
#define STAGE_B (A_STAGE_B + TILE_B)  // 49152
#define NSTAGE 4
#define GRID_P 148               // 1 CTA per SM, persistent
#define NT_U 8                   // n-tiles per work unit
#define NUNITS (128 * 8)         // (m256-tile, n-eighth) units = 1024
#define SMEM_HDR 1024            // barriers
#define SMEM_MRG 8192            // 256 rows x 4 (d,i) pairs
#define SMEM_STAGES (SMEM_HDR + SMEM_MRG)
#define SMEM_TOTAL (SMEM_STAGES + NSTAGE * STAGE_B)   // 205824

__device__ __align__(1024) __nv_bfloat16 g_A[(size_t)N_ROWS * D_DIM]; // tiled/swizzled
__device__ __align__(1024) __nv_bfloat16 g_B[(size_t)K_EMB * D_DIM];  // tiled/swizzled
__device__ float g_enorm[K_EMB];
__device__ float g_pd[(size_t)N_ROWS * 16];
__device__ int   g_pi[(size_t)N_ROWS * 16];
__device__ int   g_bestIdx[N_ROWS];

// ---------------------------------------------------------------------------
// PTX helpers (baseline features only — ptxas rejects tcgen05 on compute_103)
// ---------------------------------------------------------------------------
__device__ __forceinline__ uint32_t smem_u32(const void* p) {
    uint32_t a;
    asm("{ .reg .u64 t; cvta.to.shared.u64 t, %1; cvt.u32.u64 %0, t; }" : "=r"(a) : "l"(p));
    return a;
}
__device__ __forceinline__ void mbar_init(uint32_t m, uint32_t cnt) {
    asm volatile("mbarrier.init.shared.b64 [%0], %1;" :: "r"(m), "r"(cnt) : "memory");
}
__device__ __forceinline__ void mbar_arrive(uint32_t m) {
    asm volatile("mbarrier.arrive.shared.b64 _, [%0];" :: "r"(m) : "memory");
}
__device__ __forceinline__ void mbar_expect_tx(uint32_t m, uint32_t bytes) {
    asm volatile("mbarrier.arrive.expect_tx.shared.b64 _, [%0], %1;" :: "r"(m), "r"(bytes) : "memory");
}
__device__ __forceinline__ void mbar_wait(uint32_t m, uint32_t parity) {
    asm volatile(
        "{\n\t.reg .pred P;\n"
        "W_%=:\n\t"
        "mbarrier.try_wait.parity.acquire.cta.shared::cta.b64 P, [%0], %1, 0x989680;\n\t"
        "@P bra D_%=;\n\t"
        "bra W_%=;\n"
        "D_%=:\n\t}"
        :: "r"(m), "r"(parity) : "memory");
}
__device__ __forceinline__ void bulk_g2s(uint32_t dst, const void* src, uint32_t bytes, uint32_t mbar) {
    asm volatile(
        "cp.async.bulk.shared::cluster.global.mbarrier::complete_tx::bytes [%0], [%1], %2, [%3];"
        :: "r"(dst), "l"(src), "r"(bytes), "r"(mbar) : "memory");
}
__device__ __forceinline__ void ldsm4(uint32_t* r, uint32_t addr) {
    asm volatile("ldmatrix.sync.aligned.m8n8.x4.shared.b16 {%0,%1,%2,%3}, [%4];"
                 : "=r"(r[0]), "=r"(r[1]), "=r"(r[2]), "=r"(r[3]) : "r"(addr));
}
__device__ __forceinline__ void mma16816(float* c, const uint32_t* a, uint32_t b0, uint32_t b1) {
    asm volatile(
        "mma.sync.aligned.m16n8k16.row.col.f32.bf16.bf16.f32 "
        "{%0,%1,%2,%3}, {%4,%5,%6,%7}, {%8,%9}, {%0,%1,%2,%3};"
        : "+f"(c[0]), "+f"(c[1]), "+f"(c[2]), "+f"(c[3])
        : "r"(a[0]), "r"(a[1]), "r"(a[2]), "r"(a[3]), "r"(b0), "r"(b1));
}

// ---------------------------------------------------------------------------
// ||e_k||^2 — warp per row, float4
// ---------------------------------------------------------------------------
__global__ void enorm_kernel(const float* __restrict__ e) {
    const int row = blockIdx.x * 8 + (threadIdx.x >> 5);
    const int lane = threadIdx.x & 31;
    const float4* r4 = (const float4*)(e + (size_t)row * D_DIM);
    float s = 0.f;
#pragma unroll
    for (int d4 = lane; d4 < 128; d4 += 32) {
        float4 v = r4[d4];
        s += v.x * v.x + v.y * v.y + v.z * v.z + v.w * v.w;
    }
#pragma unroll
    for (int o = 16; o; o >>= 1) s += __shfl_down_sync(0xffffffffu, s, o);
    if (lane == 0) g_enorm[row] = s;
}

// ---------------------------------------------------------------------------
// fp32 -> bf16, pre-swizzled tile layout: tile = 128 rows x 64 cols (128B/row),
// SW128 XOR swizzle.
// ---------------------------------------------------------------------------
__device__ __forceinline__ uint4 pack8h(const float* v) {
    unsigned short hh[8];
#pragma unroll
    for (int i = 0; i < 8; i++) hh[i] = __bfloat16_as_ushort(__float2bfloat16(v[i]));
    uint4 H;
    H.x = hh[0] | ((uint32_t)hh[1] << 16); H.y = hh[2] | ((uint32_t)hh[3] << 16);
    H.z = hh[4] | ((uint32_t)hh[5] << 16); H.w = hh[6] | ((uint32_t)hh[7] << 16);
    return H;
}

__global__ void split_x_kernel(const float* __restrict__ x) {
    int gid = blockIdx.x * 256 + threadIdx.x;   // N_ROWS*64 threads
    int n = gid >> 6, d8 = gid & 63;
    const float4* xp = (const float4*)(x + (size_t)n * D_DIM + d8 * 8);
    float4 a = xp[0], b = xp[1];
    float v[8] = {a.x, a.y, a.z, a.w, b.x, b.y, b.z, b.w};
    uint4 H = pack8h(v);
    int tile = (n >> 7) * NKC + (d8 >> 3);
    int boff = (n & 127) * 128 + (d8 & 7) * 16;
    boff ^= (boff >> 3) & 0x70;
    *(uint4*)((char*)g_A + (size_t)tile * TILE_B + boff) = H;
}

__global__ void split_e_kernel(const float* __restrict__ e) {
    int gid = blockIdx.x * 256 + threadIdx.x;   // K_EMB*64 threads
    int k = gid >> 6, d8 = gid & 63;
    const float4* ep = (const float4*)(e + (size_t)k * D_DIM + d8 * 8);
    float4 a = ep[0], b = ep[1];
    float v[8] = {a.x, a.y, a.z, a.w, b.x, b.y, b.z, b.w};
    uint4 H = pack8h(v);
    int tile = (k >> 7) * NKC + (d8 >> 3);
    int boff = (k & 127) * 128 + (d8 & 7) * 16;
    boff ^= (boff >> 3) & 0x70;
    *(uint4*)((char*)g_B + (size_t)tile * TILE_B + boff) = H;
}

// ---------------------------------------------------------------------------
// Persistent HMMA GEMM + per-unit top-2 per row.
// 148 CTAs x 512 threads (1/SM). Units = (m256-tile, n-eighth), stride-148.
// BM=256 halves B traffic vs BM=128 (L2-throughput was the binding limit).
// 4-stage cp.async.bulk pipeline (48KB/stage); full[s] tx-barrier, empty[s]
// count-16. Warp grid 8(m) x 2(n); warp tile 32m x 64n (R7's proven
// per-warp schedule — register-pressure-safe).
// ---------------------------------------------------------------------------
__global__ __launch_bounds__(512, 1) void gemm_argmin_kernel() {
    extern __shared__ __align__(1024) char smem[];
    const uint32_t sb = smem_u32(smem);
    const int tid = threadIdx.x, l = tid & 31, w = tid >> 5;
    const int wm = w & 7, wn = w >> 3;
    const int b = blockIdx.x;
    const int cnt = (b < (NUNITS % GRID_P)) ? (NUNITS / GRID_P + 1) : (NUNITS / GRID_P);
    const int END = cnt * (NT_U * NKC);            // chunks in this CTA's stream

    // full[s] @ sb + s*8 ; empty[s] @ sb + 64 + s*8
    if (tid == 0) {
#pragma unroll
        for (int s = 0; s < NSTAGE; s++) { mbar_init(sb + s * 8, 1); mbar_init(sb + 64 + s * 8, 16); }
    }
    __syncthreads();

    const char* Ab = (const char*)g_A;
    const char* Bb = (const char*)g_B;
    auto issue = [&](int g) {
        int j = g >> 6, r = g & 63;
        int u = b + j * GRID_P;
        int M = u >> 3, ne = u & 7;
        int nt = ne * NT_U + (r >> 3), kc = r & 7;
        int s = g % NSTAGE;
        uint32_t st = sb + SMEM_STAGES + s * STAGE_B;
        mbar_expect_tx(sb + s * 8, STAGE_B);
        bulk_g2s(st,              Ab + ((size_t)(2 * M)     * NKC + kc) * TILE_B, TILE_B, sb + s * 8);
        bulk_g2s(st + TILE_B,     Ab + ((size_t)(2 * M + 1) * NKC + kc) * TILE_B, TILE_B, sb + s * 8);
        bulk_g2s(st + A_STAGE_B,  Bb + ((size_t)nt * NKC + kc) * TILE_B, TILE_B, sb + s * 8);
    };
    if (tid == 0) { issue(0); issue(1); issue(2); issue(3); }   // END >= 384 always

    // per-thread addressing constants
    const int lrA = (l & 7) + ((l >> 3) & 1) * 8;            // A row-in-16
    const int lrB = (l & 7) + ((l >> 4) & 1) * 8;            // B row-in-16
    const int cA  = (l >> 4);                                 // A col16 offset
    const int cB  = ((l >> 3) & 1);                           // B col16 offset
    const int swz = (l & 7);
    const uint32_t aTile = (wm >= 4) ? (uint32_t)TILE_B : 0u; // which 128-row A tile
    const uint32_t rA0 = aTile + (uint32_t)((wm & 3) * 32 + lrA) * 128;
    const uint32_t rA1 = rA0 + 16 * 128;
    uint32_t rB[4];
#pragma unroll
    for (int nb = 0; nb < 4; nb++) rB[nb] = (uint32_t)(wn * 64 + nb * 16 + lrB) * 128;

    float* sMD = (float*)(smem + SMEM_HDR);                   // [256][4]
    int*   sMI = (int*)(smem + SMEM_HDR + 256 * 4 * 4);       // [256][4]

    int g = 0;
    for (int j = 0; j < cnt; ++j) {
        const int u = b + j * GRID_P;
        const int M = u >> 3, ne = u & 7;

        float td[4][2]; int ti[4][2];
#pragma unroll
        for (int i = 0; i < 4; i++) { td[i][0] = td[i][1] = 3.4e38f; ti[i][0] = ti[i][1] = 0; }

        for (int ntl = 0; ntl < NT_U; ++ntl) {
            float acc[2][8][4];
#pragma unroll
            for (int mi = 0; mi < 2; mi++)
#pragma unroll
                for (int nf = 0; nf < 8; nf++)
#pragma unroll
                    for (int q = 0; q < 4; q++) acc[mi][nf][q] = 0.f;

            for (int kc = 0; kc < NKC; ++kc, ++g) {
                const int s = g % NSTAGE;
                const uint32_t phase = (uint32_t)((g / NSTAGE) & 1);
                mbar_wait(sb + s * 8, phase);
                const uint32_t base = sb + SMEM_STAGES + s * STAGE_B;
                const uint32_t bB = base + A_STAGE_B;
#pragma unroll
                for (int ks = 0; ks < 4; ks++) {
                    uint32_t am[2][4];
                    const uint32_t ca = ((uint32_t)((ks * 2 + cA) ^ swz)) << 4;
                    const uint32_t cb = ((uint32_t)((ks * 2 + cB) ^ swz)) << 4;
                    ldsm4(am[0], base + rA0 + ca);
                    ldsm4(am[1], base + rA1 + ca);
#pragma unroll
                    for (int nb = 0; nb < 4; nb++) {
                        uint32_t br[4];
                        ldsm4(br, bB + rB[nb] + cb);
#pragma unroll
                        for (int mi = 0; mi < 2; mi++) {
                            mma16816(acc[mi][nb * 2 + 0], am[mi], br[0], br[1]);
                            mma16816(acc[mi][nb * 2 + 1], am[mi], br[2], br[3]);
                        }
                    }
                }
                if (l == 0) mbar_arrive(sb + 64 + s * 8);     // this warp done with stage s
                if (tid == 0 && g + NSTAGE < END) {
                    mbar_wait(sb + 64 + s * 8, phase);        // all 16 warps done w/ chunk g
                    issue(g + NSTAGE);
                }
            }

            // epilogue: dist = ||e||^2 - 2*dot ; per-thread top-2 per row
            const int colb = (ne * NT_U + ntl) * BN + wn * 64 + (l & 3) * 2;
#pragma unroll
            for (int mi = 0; mi < 2; mi++)
#pragma unroll
                for (int r2 = 0; r2 < 2; r2++) {
                    const int ri = mi * 2 + r2;
#pragma unroll
                    for (int nf = 0; nf < 8; nf++)
#pragma unroll
                        for (int d = 0; d < 2; d++) {
                            const int col = colb + nf * 8 + d;
                            float dist = __ldg(&g_enorm[col]) - 2.f * acc[mi][nf][r2 * 2 + d];
                            if (dist < td[ri][0]) {
                                td[ri][1] = td[ri][0]; ti[ri][1] = ti[ri][0];
                                td[ri][0] = dist;      ti[ri][0] = col;
                            } else if (dist < td[ri][1]) {
                                td[ri][1] = dist; ti[ri][1] = col;
                            }
                        }
                }
        }

        // intra-warp merge: 4-lane groups (same rows, different cols) -> top-2
#pragma unroll
        for (int ri = 0; ri < 4; ++ri) {
            float d0 = td[ri][0], d1 = td[ri][1];
            int   i0 = ti[ri][0], i1 = ti[ri][1];
#pragma unroll
            for (int off = 1; off <= 2; off <<= 1) {
                float od0 = __shfl_xor_sync(0xffffffffu, d0, off);
                float od1 = __shfl_xor_sync(0xffffffffu, d1, off);
                int   oi0 = __shfl_xor_sync(0xffffffffu, i0, off);
                int   oi1 = __shfl_xor_sync(0xffffffffu, i1, off);
                if (od0 < d0 || (od0 == d0 && oi0 < i0)) {
                    float nd1; int ni1;
                    if (d0 < od1 || (d0 == od1 && i0 < oi1)) { nd1 = d0; ni1 = i0; }
                    else                                      { nd1 = od1; ni1 = oi1; }
                    d0 = od0; i0 = oi0; d1 = nd1; i1 = ni1;
                } else if (od0 < d1 || (od0 == d1 && oi0 < i1)) {
                    d1 = od0; i1 = oi0;
                }
            }
            if ((l & 3) == 0) {
                const int row = wm * 32 + (ri >> 1) * 16 + (ri & 1) * 8 + (l >> 2);
                sMD[row * 4 + wn * 2]     = d0; sMI[row * 4 + wn * 2]     = i0;
                sMD[row * 4 + wn * 2 + 1] = d1; sMI[row * 4 + wn * 2 + 1] = i1;
            }
        }
        __syncthreads();
        if (tid < BM) {
            float dv[4]; int iv[4];
#pragma unroll
            for (int t = 0; t < 4; t++) { dv[t] = sMD[tid * 4 + t]; iv[t] = sMI[tid * 4 + t]; }
            const size_t rg = (size_t)(M * BM + tid) * 16 + ne * 2;
#pragma unroll
            for (int q = 0; q < 2; q++) {
                float bd = dv[0]; int bi = iv[0], bt = 0;
#pragma unroll
                for (int t = 1; t < 4; t++)
                    if (dv[t] < bd || (dv[t] == bd && iv[t] < bi)) { bd = dv[t]; bi = iv[t]; bt = t; }
                g_pd[rg + q] = bd; g_pi[rg + q] = bi;
                dv[bt] = 3.4e38f;
            }
        }
        __syncthreads();   // protect sMD/sMI reuse by next unit
    }
}

// ---------------------------------------------------------------------------
// Fused tail: top-4 of 16 candidates -> exact fp32 rescore -> writeout.
// One warp per row.
// ---------------------------------------------------------------------------
__global__ void candwrite_kernel(const float* __restrict__ x,
                                 const float* __restrict__ e,
                                 float* __restrict__ out) {
    const int row = blockIdx.x * 8 + (threadIdx.x >> 5);
    const int lane = threadIdx.x & 31;

    int c[4];
    if (lane == 0) {
        float dv[16]; int iv[16];
#pragma unroll
        for (int t = 0; t < 16; t++) {
            dv[t] = g_pd[(size_t)row * 16 + t];
            iv[t] = g_pi[(size_t)row * 16 + t];
        }
#pragma unroll
        for (int q = 0; q < 4; q++) {
            float bd = dv[0]; int bi = iv[0], bt = 0;
#pragma unroll
            for (int t = 1; t < 16; t++)
                if (dv[t] < bd || (dv[t] == bd && iv[t] < bi)) { bd = dv[t]; bi = iv[t]; bt = t; }
            c[q] = bi;
            dv[bt] = 3.4e38f;
        }
    }
#pragma unroll
    for (int q = 0; q < 4; q++) c[q] = __shfl_sync(0xffffffffu, c[q], 0);

    const float4* x4 = (const float4*)(x + (size_t)row * D_DIM);
    float s[4] = {0.f, 0.f, 0.f, 0.f};
#pragma unroll
    for (int d4 = lane; d4 < 128; d4 += 32) {
        float4 xv = x4[d4];
#pragma unroll
        for (int q = 0; q < 4; q++) {
            float4 ev = ((const float4*)(e + (size_t)c[q] * D_DIM))[d4];
            s[q] += xv.x * ev.x + xv.y * ev.y + xv.z * ev.z + xv.w * ev.w;
        }
    }
#pragma unroll
    for (int o = 16; o; o >>= 1)
#pragma unroll
        for (int q = 0; q < 4; q++) s[q] += __shfl_down_sync(0xffffffffu, s[q], o);

    int best = 0;
    if (lane == 0) {
        float bd = 3.4e38f; int bi = 0x7fffffff;
#pragma unroll
        for (int q = 0; q < 4; q++) {
            float dq = g_enorm[c[q]] - 2.f * s[q];
            if (dq < bd || (dq == bd && c[q] < bi)) { bd = dq; bi = c[q]; }
        }
        best = bi;
        g_bestIdx[row] = bi;
    }
    best = __shfl_sync(0xffffffffu, best, 0);

    const int ND4 = N_ROWS * (D_DIM / 4);
    const float4* e4 = (const float4*)(e + (size_t)best * D_DIM);
    float4* o4 = (float4*)out;
#pragma unroll
    for (int d4 = lane; d4 < 128; d4 += 32) {
        float4 xv = x4[d4];
        float4 ev = e4[d4];
        float4 xq;
        xq.x = xv.x + (ev.x - xv.x);
        xq.y = xv.y + (ev.y - xv.y);
        xq.z = xv.z + (ev.z - xv.z);
        xq.w = xv.w + (ev.w - xv.w);
        const int i = row * 128 + d4;
        o4[i] = xq;               // x_q
        o4[ND4 + i] = xv;         // z_e
        o4[2 * ND4 + i] = ev;     // z_q
    }
}

extern "C" void kernel_launch(void* const* d_in, const int* in_sizes, int n_in,
                              void* d_out, int out_size) {
    const float* x = (const float*)d_in[0];
    const float* e = (const float*)d_in[1];
    float* out = (float*)d_out;

    cudaFuncSetAttribute(gemm_argmin_kernel,
                         cudaFuncAttributeMaxDynamicSharedMemorySize, SMEM_TOTAL);

    split_x_kernel<<<N_ROWS * 64 / 256, 256>>>(x);
    split_e_kernel<<<K_EMB * 64 / 256, 256>>>(e);
    enorm_kernel<<<K_EMB / 8, 256>>>(e);
    gemm_argmin_kernel<<<GRID_P, 512, SMEM_TOTAL>>>();
    candwrite_kernel<<<N_ROWS / 8, 256>>>(x, e, out);
}